// round 15
// baseline (speedup 1.0000x reference)
#include <cuda_runtime.h>

#define BATCH 256
#define EDIM  128
#define HDIM  256
#define VOCAB 32000
#define G4H   1024   // 4*H
#define ODIM  2
#define NCTA  128    // 8 clusters x 16 CTAs; cluster = one 32-row batch tile
#define CLUSTER 16
#define DSMEM (32768 + 65536)   // hS[256][32] + wW plain pairs [8][256][2x ull2]

// ---------------- scratch (device globals; no runtime allocation) -----------
__device__ float g_proj[(size_t)VOCAB * G4H];  // emb@w_ih^T + bias  (131 MB)
__device__ float g_h[2][HDIM][BATCH];          // double-buffered h, TRANSPOSED [j][b]
__device__ float g_lasth[BATCH][HDIM];         // last valid h (for decode)

// ---------------- asm helpers ------------------------------------------------
__device__ __forceinline__ void ffma2(unsigned long long& d,
                                      unsigned long long a, unsigned long long b) {
    asm("fma.rn.f32x2 %0, %1, %2, %0;" : "+l"(d) : "l"(a), "l"(b));
}
__device__ __forceinline__ float2 unpk(unsigned long long v) {
    float2 r; asm("mov.b64 {%0,%1}, %2;" : "=f"(r.x), "=f"(r.y) : "l"(v)); return r;
}
__device__ __forceinline__ unsigned long long dup2(float x) {
    unsigned long long r; asm("mov.b64 %0, {%1,%1};" : "=l"(r) : "f"(x)); return r;
}
__device__ __forceinline__ void cpa16(unsigned dst, const void* src) {
    asm volatile("cp.async.cg.shared.global [%0], [%1], 16;" :: "r"(dst), "l"(src));
}
__device__ __forceinline__ void cluster_arrive() {
    asm volatile("barrier.cluster.arrive.aligned;" ::: "memory");
}
__device__ __forceinline__ void cluster_wait() {
    asm volatile("barrier.cluster.wait.aligned;" ::: "memory");
}

// ---------------- kernel 1: proj_table = emb @ w_ih^T + (b_ih + b_hh) -------
__global__ void __launch_bounds__(256) prep_proj_kernel(
    const float* __restrict__ emb, const float* __restrict__ w_ih,
    const float* __restrict__ b_ih, const float* __restrict__ b_hh)
{
    __shared__ float sA[64][65];   // sA[k][v]
    __shared__ float sW[64][65];   // sW[k][c]
    const int cb = blockIdx.x & 15, vb = blockIdx.x >> 4;
    const int vbase = vb * 64, cbase = cb * 64;
    const int tid = threadIdx.x;
    const int c0 = (tid & 15) * 4, v0 = (tid >> 4) * 4;

    float acc[4][4];
#pragma unroll
    for (int i = 0; i < 4; i++)
#pragma unroll
        for (int j = 0; j < 4; j++) acc[i][j] = 0.0f;

    for (int kc = 0; kc < EDIM; kc += 64) {
#pragma unroll
        for (int r = 0; r < 16; r++) {
            int idx = tid + r * 256;
            int row = idx >> 6, kk = idx & 63;
            sA[kk][row] = emb [(vbase + row) * EDIM + kc + kk];
            sW[kk][row] = w_ih[(cbase + row) * EDIM + kc + kk];
        }
        __syncthreads();
#pragma unroll 8
        for (int k = 0; k < 64; k++) {
            float a0 = sA[k][v0], a1 = sA[k][v0+1], a2 = sA[k][v0+2], a3 = sA[k][v0+3];
            float w0 = sW[k][c0], w1 = sW[k][c0+1], w2 = sW[k][c0+2], w3 = sW[k][c0+3];
            acc[0][0]+=a0*w0; acc[0][1]+=a0*w1; acc[0][2]+=a0*w2; acc[0][3]+=a0*w3;
            acc[1][0]+=a1*w0; acc[1][1]+=a1*w1; acc[1][2]+=a1*w2; acc[1][3]+=a1*w3;
            acc[2][0]+=a2*w0; acc[2][1]+=a2*w1; acc[2][2]+=a2*w2; acc[2][3]+=a2*w3;
            acc[3][0]+=a3*w0; acc[3][1]+=a3*w1; acc[3][2]+=a3*w2; acc[3][3]+=a3*w3;
        }
        __syncthreads();
    }
    float bias[4];
#pragma unroll
    for (int j = 0; j < 4; j++) bias[j] = b_ih[cbase + c0 + j] + b_hh[cbase + c0 + j];
#pragma unroll
    for (int i = 0; i < 4; i++) {
        float4 v = make_float4(acc[i][0]+bias[0], acc[i][1]+bias[1],
                               acc[i][2]+bias[2], acc[i][3]+bias[3]);
        *(float4*)&g_proj[(size_t)(vbase + v0 + i) * G4H + cbase + c0] = v;
    }
}

// ---------------- kernel 2: persistent LSTM recurrence ----------------------
// 8 independent clusters of 16 CTAs. Cluster = 32 batch rows; CTA (= cluster
// rank) owns 16 hidden units (64 gate cols). Per-step sync = HW cluster barrier.
__global__ void __launch_bounds__(256) lstm_kernel(
    const int*   __restrict__ inp,      // [S, B] time-major
    const int*   __restrict__ lengths,  // [B]
    const float* __restrict__ h0,       // [1, B, H]
    const float* __restrict__ c0,       // [1, B, H]
    const float* __restrict__ w_hh,     // [4H, H]
    float*       __restrict__ out,      // decoded(512) | last_h(65536) | last_c(65536)
    int wstate)
{
    extern __shared__ __align__(16) char dsm[];
    float*      hS = (float*)dsm;                  // [256][32] staged h
    ulonglong2* wW = (ulonglong2*)(dsm + 32768);   // [8 warps][256 j][2]: (wc,wc+1) pairs
    __shared__ float gS[32][65];                   // gates [b_local][g*16+u]
    __shared__ int   lenS[32];
    __shared__ int   sMax;

    const int tid  = threadIdx.x;
    const int wid  = tid >> 5;
    const int lane = tid & 31;
    const int ut   = blockIdx.x & 15;   // cluster rank = unit tile
    const int bt   = blockIdx.x >> 4;   // cluster id = batch tile
    const int b0   = bt * 32;
    const int hu0  = ut * 16;

    if (tid == 0) sMax = 0;
    __syncthreads();
    atomicMax(&sMax, lengths[b0 + (tid & 31)]);     // per-cluster max (same in all 16 CTAs)
    if (tid < 32) lenS[tid] = lengths[b0 + tid];

    // fill wW: 8192 plain pairs (w[c], w[c+1]); float offset (w*256+j)*8 + 2k
    {
        float* wf = (float*)wW;
        for (int p = tid; p < 8192; p += 256) {
            int w_ = p >> 10, rem = p & 1023, j = rem >> 2, k = rem & 3;
            int c  = 8 * w_ + 2 * k;
            int gc = (c >> 4) * HDIM + hu0 + (c & 15);
            wf[(w_ * 256 + j) * 8 + 2 * k    ] = w_hh[gc * HDIM + j];
            wf[(w_ * 256 + j) * 8 + 2 * k + 1] = w_hh[(gc + 1) * HDIM + j];
        }
    }
    // init c registers and h buffer 0 (transposed) for this CTA's slice
    const int pb = tid & 31;            // pointwise batch row
    const int pu = tid >> 5;            // owns units pu, pu+8
    float creg0 = c0[(b0 + pb) * HDIM + hu0 + pu];
    float creg1 = c0[(b0 + pb) * HDIM + hu0 + pu + 8];
    for (int p = tid; p < 512; p += 256) {
        int b = p & 31, u = p >> 5;
        g_h[0][hu0 + u][b0 + b] = h0[(b0 + b) * HDIM + hu0 + u];
    }
    __syncthreads();
    const int maxlen = sMax;

    // proj row base for this thread's 8 contiguous gate cols (same gate block)
    const int pcol = ((8 * wid) >> 4) * HDIM + hu0 + ((8 * wid) & 15);
    const unsigned hSaddr = (unsigned)__cvta_generic_to_shared(dsm);

    // h[0] visible cluster-wide; prefetch t=0 x-part under the barrier
    cluster_arrive();
    float4 xq0, xq1;
    {
        int tok = __ldg(&inp[0 * BATCH + b0 + lane]);
        const float* pr = &g_proj[(size_t)tok * G4H + pcol];
        xq0 = *(const float4*)pr;  xq1 = *(const float4*)(pr + 4);
    }
    cluster_wait();

    int cur = 0;
    for (int t = 0; t < maxlen; t++) {
        // ---- stage h[cur] (32 KB) in 2 chunks via cp.async.cg (L2, fresh) ----
#pragma unroll
        for (int ch = 0; ch < 2; ch++) {
#pragma unroll
            for (int r = 0; r < 4; r++) {
                int s = tid + r * 256;               // seg in chunk (1024 segs x 16B)
                int j = ch * 128 + (s >> 3);
                int bo = (s & 7) * 4;
                cpa16(hSaddr + ch * 16384 + s * 16, &g_h[cur][j][b0 + bo]);
            }
            asm volatile("cp.async.commit_group;");
        }

        // ---- recurrent GEMM: lane=batch, warp-uniform w, f32x2 core ----------
        unsigned long long a0 = 0ull, a1 = 0ull, a2 = 0ull, a3 = 0ull;
        asm volatile("cp.async.wait_group 1;");
        __syncthreads();                             // chunk 0 visible
#pragma unroll
        for (int ch = 0; ch < 2; ch++) {
            const float*      hp = hS + ch * 128 * 32 + lane;
            const ulonglong2* wp = wW + (wid * 256 + ch * 128) * 2;
#pragma unroll 8
            for (int jj = 0; jj < 128; jj++) {
                unsigned long long h2 = dup2(hp[jj * 32]);   // LDS.32 + mov.b64
                ulonglong2 wa = wp[jj * 2];                  // bcast LDS.128 (cols +0..3)
                ulonglong2 wb = wp[jj * 2 + 1];              // bcast LDS.128 (cols +4..7)
                ffma2(a0, h2, wa.x); ffma2(a1, h2, wa.y);
                ffma2(a2, h2, wb.x); ffma2(a3, h2, wb.y);
            }
            if (ch == 0) {
                asm volatile("cp.async.wait_group 0;");
                __syncthreads();                     // chunk 1 visible
            }
        }

        // ---- add x-part, stage gates (conflict-free: bank = lane) ------------
        {
            float2 f0 = unpk(a0), f1 = unpk(a1), f2 = unpk(a2), f3 = unpk(a3);
            float* g = &gS[lane][8 * wid];
            g[0] = f0.x + xq0.x;  g[1] = f0.y + xq0.y;
            g[2] = f1.x + xq0.z;  g[3] = f1.y + xq0.w;
            g[4] = f2.x + xq1.x;  g[5] = f2.y + xq1.y;
            g[6] = f3.x + xq1.z;  g[7] = f3.y + xq1.w;
        }
        __syncthreads();

        // ---- pointwise cell: this thread owns (pb, pu) and (pb, pu+8) --------
        const int nxt = cur ^ 1;
        const int lastt = lenS[pb] - 1;
#pragma unroll
        for (int r = 0; r < 2; r++) {
            int u = pu + 8 * r;
            float gi = gS[pb][u],      gf = gS[pb][16 + u];
            float gc = gS[pb][32 + u], go = gS[pb][48 + u];
            float si = 1.0f / (1.0f + __expf(-gi));
            float sf = 1.0f / (1.0f + __expf(-gf));
            float so = 1.0f / (1.0f + __expf(-go));
            float tg = tanhf(gc);
            float cn = sf * (r ? creg1 : creg0) + si * tg;
            float hn = so * tanhf(cn);
            if (r) creg1 = cn; else creg0 = cn;
            int gb = b0 + pb, jj = hu0 + u;
            g_h[nxt][jj][gb] = hn;
            if (t == lastt) {
                g_lasth[gb][jj] = hn;
                if (wstate) {
                    out[ODIM*BATCH + gb*HDIM + jj] = hn;                 // last_h
                    out[ODIM*BATCH + BATCH*HDIM + gb*HDIM + jj] = cn;    // last_c
                }
            }
        }

        // ---- arrive (releases h stores), prefetch next xp under barrier ------
        cluster_arrive();
        if (t + 1 < maxlen) {
            int tok = __ldg(&inp[(t + 1) * BATCH + b0 + lane]);
            const float* pr = &g_proj[(size_t)tok * G4H + pcol];
            xq0 = *(const float4*)pr;  xq1 = *(const float4*)(pr + 4);
        }
        cluster_wait();
        cur = nxt;
    }
}

// ---------------- kernel 3: decoded = sigmoid(last_h @ dec_w^T) -------------
__global__ void __launch_bounds__(256) decode_kernel(
    const float* __restrict__ dec_w, float* __restrict__ out)
{
    int w = (blockIdx.x * blockDim.x + threadIdx.x) >> 5;   // global warp id
    int lane = threadIdx.x & 31;
    if (w >= BATCH * ODIM) return;
    int b = w >> 1, o = w & 1;
    float s = 0.0f;
#pragma unroll
    for (int j = lane; j < HDIM; j += 32) s += g_lasth[b][j] * dec_w[o * HDIM + j];
#pragma unroll
    for (int off = 16; off; off >>= 1) s += __shfl_xor_sync(0xFFFFFFFFu, s, off);
    if (lane == 0) out[b * ODIM + o] = 1.0f / (1.0f + __expf(-s));
}

// ---------------- launcher --------------------------------------------------
extern "C" void kernel_launch(void* const* d_in, const int* in_sizes, int n_in,
                              void* d_out, int out_size) {
    const int*   inp     = (const int*)  d_in[0];
    const int*   lengths = (const int*)  d_in[1];
    const float* h0      = (const float*)d_in[2];
    const float* c0      = (const float*)d_in[3];
    const float* emb     = (const float*)d_in[4];
    const float* w_ih    = (const float*)d_in[5];
    const float* w_hh    = (const float*)d_in[6];
    const float* b_ih    = (const float*)d_in[7];
    const float* b_hh    = (const float*)d_in[8];
    const float* dec_w   = (const float*)d_in[9];
    float* out = (float*)d_out;
    int wstate = (out_size >= ODIM * BATCH + 2 * BATCH * HDIM) ? 1 : 0;

    cudaFuncSetAttribute(lstm_kernel, cudaFuncAttributeMaxDynamicSharedMemorySize, DSMEM);
    cudaFuncSetAttribute(lstm_kernel, cudaFuncAttributeNonPortableClusterSizeAllowed, 1);

    prep_proj_kernel<<<500 * 16, 256>>>(emb, w_ih, b_ih, b_hh);

    cudaLaunchConfig_t cfg = {};
    cfg.gridDim  = dim3(NCTA, 1, 1);
    cfg.blockDim = dim3(256, 1, 1);
    cfg.dynamicSmemBytes = DSMEM;
    cfg.stream = 0;
    cudaLaunchAttribute attr[1];
    attr[0].id = cudaLaunchAttributeClusterDimension;
    attr[0].val.clusterDim.x = CLUSTER;
    attr[0].val.clusterDim.y = 1;
    attr[0].val.clusterDim.z = 1;
    cfg.attrs = attr;
    cfg.numAttrs = 1;
    cudaLaunchKernelEx(&cfg, lstm_kernel, inp, lengths, h0, c0, w_hh, out, wstate);

    decode_kernel<<<64, 256>>>(dec_w, out);
}

// round 16
// speedup vs baseline: 1.3129x; 1.3129x over previous
#include <cuda_runtime.h>

#define BATCH 256
#define EDIM  128
#define HDIM  256
#define VOCAB 32000
#define G4H   1024   // 4*H
#define ODIM  2
#define NCTA  128    // 8 groups x 16 CTAs; group = one 32-row batch tile
#define NGRP  8
#define GSZ   16
#define DSMEM (32768 + 131072)  // hS[256][32] + wW dup'd pairs [8][256][4] ull2

// ---------------- scratch (device globals; no runtime allocation) -----------
__device__ float    g_proj[(size_t)VOCAB * G4H];  // emb@w_ih^T + bias  (131 MB)
__device__ float    g_h[2][HDIM][BATCH];          // double-buffered h, TRANSPOSED [j][b]
__device__ float    g_lasth[BATCH][HDIM];         // last valid h (for decode)
__device__ unsigned g_bar_gen[NGRP][32];          // per-group gen (128B stride)
__device__ unsigned g_bar_cnt[NGRP][32];          // per-group arrival counter

// ---------------- asm helpers ------------------------------------------------
__device__ __forceinline__ void ffma2(unsigned long long& d,
                                      unsigned long long a, unsigned long long b) {
    asm("fma.rn.f32x2 %0, %1, %2, %0;" : "+l"(d) : "l"(a), "l"(b));
}
__device__ __forceinline__ float2 unpk(unsigned long long v) {
    float2 r; asm("mov.b64 {%0,%1}, %2;" : "=f"(r.x), "=f"(r.y) : "l"(v)); return r;
}
__device__ __forceinline__ void cpa16(unsigned dst, const void* src) {
    asm volatile("cp.async.cg.shared.global [%0], [%1], 16;" :: "r"(dst), "l"(src));
}
__device__ __forceinline__ unsigned atom_add_acqrel(unsigned* p) {
    unsigned old;
    asm volatile("atom.acq_rel.gpu.global.add.u32 %0, [%1], 1;"
                 : "=r"(old) : "l"(p) : "memory");
    return old;
}
__device__ __forceinline__ void st_release(unsigned* p, unsigned v) {
    asm volatile("st.release.gpu.global.u32 [%0], %1;" :: "l"(p), "r"(v) : "memory");
}
__device__ __forceinline__ unsigned ld_acquire(unsigned* p) {
    unsigned v;
    asm volatile("ld.acquire.gpu.global.u32 %0, [%1];" : "=r"(v) : "l"(p) : "memory");
    return v;
}

// ---------------- per-group barrier (16 arrivals; monotonic; replay-safe) ----
__device__ __forceinline__ void group_barrier(unsigned* gen, unsigned* cnt, unsigned target) {
    __syncthreads();
    if (threadIdx.x == 0) {
        unsigned arrived = atom_add_acqrel(cnt);    // release my CTA's writes
        if (arrived == GSZ - 1) {
            *cnt = 0u;                              // ordered before gen by release
            st_release(gen, target);
        } else {
            while ((int)(ld_acquire(gen) - target) < 0) { }
        }
    }
    __syncthreads();
}

// ---------------- kernel 1: proj_table = emb @ w_ih^T + (b_ih + b_hh) -------
__global__ void __launch_bounds__(256) prep_proj_kernel(
    const float* __restrict__ emb, const float* __restrict__ w_ih,
    const float* __restrict__ b_ih, const float* __restrict__ b_hh)
{
    __shared__ float sA[64][65];   // sA[k][v]
    __shared__ float sW[64][65];   // sW[k][c]
    const int cb = blockIdx.x & 15, vb = blockIdx.x >> 4;
    const int vbase = vb * 64, cbase = cb * 64;
    const int tid = threadIdx.x;
    const int c0 = (tid & 15) * 4, v0 = (tid >> 4) * 4;

    float acc[4][4];
#pragma unroll
    for (int i = 0; i < 4; i++)
#pragma unroll
        for (int j = 0; j < 4; j++) acc[i][j] = 0.0f;

    for (int kc = 0; kc < EDIM; kc += 64) {
#pragma unroll
        for (int r = 0; r < 16; r++) {
            int idx = tid + r * 256;
            int row = idx >> 6, kk = idx & 63;
            sA[kk][row] = emb [(vbase + row) * EDIM + kc + kk];
            sW[kk][row] = w_ih[(cbase + row) * EDIM + kc + kk];
        }
        __syncthreads();
#pragma unroll 8
        for (int k = 0; k < 64; k++) {
            float a0 = sA[k][v0], a1 = sA[k][v0+1], a2 = sA[k][v0+2], a3 = sA[k][v0+3];
            float w0 = sW[k][c0], w1 = sW[k][c0+1], w2 = sW[k][c0+2], w3 = sW[k][c0+3];
            acc[0][0]+=a0*w0; acc[0][1]+=a0*w1; acc[0][2]+=a0*w2; acc[0][3]+=a0*w3;
            acc[1][0]+=a1*w0; acc[1][1]+=a1*w1; acc[1][2]+=a1*w2; acc[1][3]+=a1*w3;
            acc[2][0]+=a2*w0; acc[2][1]+=a2*w1; acc[2][2]+=a2*w2; acc[2][3]+=a2*w3;
            acc[3][0]+=a3*w0; acc[3][1]+=a3*w1; acc[3][2]+=a3*w2; acc[3][3]+=a3*w3;
        }
        __syncthreads();
    }
    float bias[4];
#pragma unroll
    for (int j = 0; j < 4; j++) bias[j] = b_ih[cbase + c0 + j] + b_hh[cbase + c0 + j];
#pragma unroll
    for (int i = 0; i < 4; i++) {
        float4 v = make_float4(acc[i][0]+bias[0], acc[i][1]+bias[1],
                               acc[i][2]+bias[2], acc[i][3]+bias[3]);
        *(float4*)&g_proj[(size_t)(vbase + v0 + i) * G4H + cbase + c0] = v;
    }
}

// ---------------- kernel 2: persistent LSTM recurrence ----------------------
// 8 independent groups of 16 CTAs. Group = 32 batch rows; CTA owns 16 hidden
// units (64 gate cols). lane = (row-quad rq, col-pair cp): h LDS.128 (1 phase),
// w dup'd LDS.128 (1 phase), 4x fma.rn.f32x2 per j.
__global__ void __launch_bounds__(256) lstm_kernel(
    const int*   __restrict__ inp,      // [S, B] time-major
    const int*   __restrict__ lengths,  // [B]
    const float* __restrict__ h0,       // [1, B, H]
    const float* __restrict__ c0,       // [1, B, H]
    const float* __restrict__ w_hh,     // [4H, H]
    float*       __restrict__ out,      // decoded(512) | last_h(65536) | last_c(65536)
    int wstate)
{
    extern __shared__ __align__(16) char dsm[];
    float*      hS = (float*)dsm;                  // [256][32] staged h
    ulonglong2* wW = (ulonglong2*)(dsm + 32768);   // [8][256][4]: ((wc,wc),(wc1,wc1))
    __shared__ float gS[32][65];                   // gates [b_local][g*16+u]
    __shared__ int   lenS[32];
    __shared__ int   sMax;

    const int tid  = threadIdx.x;
    const int wid  = tid >> 5;
    const int lane = tid & 31;
    const int ut   = blockIdx.x & 15;   // unit tile (rank within group)
    const int bt   = blockIdx.x >> 4;   // group id = batch tile
    const int b0   = bt * 32;
    const int hu0  = ut * 16;

    unsigned* barGen = &g_bar_gen[bt][0];
    unsigned* barCnt = &g_bar_cnt[bt][0];

    if (tid == 0) sMax = 0;
    __syncthreads();
    atomicMax(&sMax, lengths[b0 + (tid & 31)]);     // per-group max (same in all 16 CTAs)
    if (tid < 32) lenS[tid] = lengths[b0 + tid];
    __shared__ unsigned sBase;
    if (tid == 0) sBase = *(volatile unsigned*)barGen;

    // fill wW: [wid][j][cp] = ((w[c],w[c]),(w[c+1],w[c+1])), c = 8*wid + 2*cp
    {
        float* wf = (float*)wW;
        for (int p = tid; p < 8192; p += 256) {
            int w_ = p >> 10, rem = p & 1023, j = rem >> 2, cp = rem & 3;
            int c  = 8 * w_ + 2 * cp;
            int gc = (c >> 4) * HDIM + hu0 + (c & 15);
            float w0 = w_hh[gc * HDIM + j];
            float w1 = w_hh[(gc + 1) * HDIM + j];
            wf[p * 4 + 0] = w0;  wf[p * 4 + 1] = w0;
            wf[p * 4 + 2] = w1;  wf[p * 4 + 3] = w1;
        }
    }
    // init c registers and h buffer 0 (transposed) for this CTA's slice
    const int pb = tid & 31;            // pointwise batch row
    const int pu = tid >> 5;            // owns units pu, pu+8
    float creg0 = c0[(b0 + pb) * HDIM + hu0 + pu];
    float creg1 = c0[(b0 + pb) * HDIM + hu0 + pu + 8];
    for (int p = tid; p < 512; p += 256) {
        int b = p & 31, u = p >> 5;
        g_h[0][hu0 + u][b0 + b] = h0[(b0 + b) * HDIM + hu0 + u];
    }
    __syncthreads();
    const int      maxlen = sMax;
    const unsigned base   = sBase;

    // GEMM mapping: rq = lane&7 (rows 4rq..4rq+3), cp = lane>>3 (cols 2cp,2cp+1 of warp's 8)
    const int rq = lane & 7;
    const int cp = lane >> 3;
    const int c  = 8 * wid + 2 * cp;                 // CTA-local gate col (even)
    const int pcol = (c >> 4) * HDIM + hu0 + (c & 15);  // g_proj col for (c, c+1)
    const unsigned hSaddr = (unsigned)__cvta_generic_to_shared(dsm);

    // prefetch x-part for t=0: 4 rows x (col c, c+1)
    float2 xp0, xp1, xp2, xp3;
    {
        const int* ip = &inp[0 * BATCH + b0 + 4 * rq];
        xp0 = *(const float2*)&g_proj[(size_t)__ldg(ip+0) * G4H + pcol];
        xp1 = *(const float2*)&g_proj[(size_t)__ldg(ip+1) * G4H + pcol];
        xp2 = *(const float2*)&g_proj[(size_t)__ldg(ip+2) * G4H + pcol];
        xp3 = *(const float2*)&g_proj[(size_t)__ldg(ip+3) * G4H + pcol];
    }
    group_barrier(barGen, barCnt, base + 1);         // h[0] visible group-wide

    int cur = 0;
    for (int t = 0; t < maxlen; t++) {
        // ---- stage h[cur] (32 KB) in 2 chunks via cp.async.cg (L2, fresh) ----
#pragma unroll
        for (int ch = 0; ch < 2; ch++) {
#pragma unroll
            for (int r = 0; r < 4; r++) {
                int s = tid + r * 256;               // seg in chunk (1024 segs x 16B)
                int j = ch * 128 + (s >> 3);
                int bo = (s & 7) * 4;
                cpa16(hSaddr + ch * 16384 + s * 16, &g_h[cur][j][b0 + bo]);
            }
            asm volatile("cp.async.commit_group;");
        }

        // ---- recurrent GEMM: 2 wavefronts + 4 FFMA2 per j ---------------------
        unsigned long long a00 = 0ull, a01 = 0ull, a10 = 0ull, a11 = 0ull;
        asm volatile("cp.async.wait_group 1;");
        __syncthreads();                             // chunk 0 visible
#pragma unroll
        for (int ch = 0; ch < 2; ch++) {
            const char*       hp = dsm + ch * 16384 + rq * 16;
            const ulonglong2* wp = wW + (wid * 256 + ch * 128) * 4 + cp;
#pragma unroll 8
            for (int jj = 0; jj < 128; jj++) {
                ulonglong2 hv = *(const ulonglong2*)(hp + jj * 128); // rows 4rq..4rq+3
                ulonglong2 wv = wp[jj * 4];                          // ((wc,wc),(wc1,wc1))
                ffma2(a00, hv.x, wv.x); ffma2(a01, hv.x, wv.y);
                ffma2(a10, hv.y, wv.x); ffma2(a11, hv.y, wv.y);
            }
            if (ch == 0) {
                asm volatile("cp.async.wait_group 0;");
                __syncthreads();                     // chunk 1 visible
            }
        }

        // ---- add x-part, stage gates -----------------------------------------
        {
            float2 f00 = unpk(a00), f01 = unpk(a01), f10 = unpk(a10), f11 = unpk(a11);
            gS[4*rq+0][c] = f00.x + xp0.x;  gS[4*rq+0][c+1] = f01.x + xp0.y;
            gS[4*rq+1][c] = f00.y + xp1.x;  gS[4*rq+1][c+1] = f01.y + xp1.y;
            gS[4*rq+2][c] = f10.x + xp2.x;  gS[4*rq+2][c+1] = f11.x + xp2.y;
            gS[4*rq+3][c] = f10.y + xp3.x;  gS[4*rq+3][c+1] = f11.y + xp3.y;
        }
        __syncthreads();

        // ---- pointwise cell: this thread owns (pb, pu) and (pb, pu+8) --------
        const int nxt = cur ^ 1;
        const int lastt = lenS[pb] - 1;
#pragma unroll
        for (int r = 0; r < 2; r++) {
            int u = pu + 8 * r;
            float gi = gS[pb][u],      gf = gS[pb][16 + u];
            float gc = gS[pb][32 + u], go = gS[pb][48 + u];
            float si = 1.0f / (1.0f + __expf(-gi));
            float sf = 1.0f / (1.0f + __expf(-gf));
            float so = 1.0f / (1.0f + __expf(-go));
            float tg = tanhf(gc);
            float cn = sf * (r ? creg1 : creg0) + si * tg;
            float hn = so * tanhf(cn);
            if (r) creg1 = cn; else creg0 = cn;
            int gb = b0 + pb, jj = hu0 + u;
            g_h[nxt][jj][gb] = hn;
            if (t == lastt) {
                g_lasth[gb][jj] = hn;
                if (wstate) {
                    out[ODIM*BATCH + gb*HDIM + jj] = hn;                 // last_h
                    out[ODIM*BATCH + BATCH*HDIM + gb*HDIM + jj] = cn;    // last_c
                }
            }
        }

        // ---- prefetch next step's x-part, then group barrier ------------------
        if (t + 1 < maxlen) {
            const int* ip = &inp[(t + 1) * BATCH + b0 + 4 * rq];
            xp0 = *(const float2*)&g_proj[(size_t)__ldg(ip+0) * G4H + pcol];
            xp1 = *(const float2*)&g_proj[(size_t)__ldg(ip+1) * G4H + pcol];
            xp2 = *(const float2*)&g_proj[(size_t)__ldg(ip+2) * G4H + pcol];
            xp3 = *(const float2*)&g_proj[(size_t)__ldg(ip+3) * G4H + pcol];
        }
        group_barrier(barGen, barCnt, base + 2 + t);
        cur = nxt;
    }
}

// ---------------- kernel 3: decoded = sigmoid(last_h @ dec_w^T) -------------
__global__ void __launch_bounds__(256) decode_kernel(
    const float* __restrict__ dec_w, float* __restrict__ out)
{
    int w = (blockIdx.x * blockDim.x + threadIdx.x) >> 5;   // global warp id
    int lane = threadIdx.x & 31;
    if (w >= BATCH * ODIM) return;
    int b = w >> 1, o = w & 1;
    float s = 0.0f;
#pragma unroll
    for (int j = lane; j < HDIM; j += 32) s += g_lasth[b][j] * dec_w[o * HDIM + j];
#pragma unroll
    for (int off = 16; off; off >>= 1) s += __shfl_xor_sync(0xFFFFFFFFu, s, off);
    if (lane == 0) out[b * ODIM + o] = 1.0f / (1.0f + __expf(-s));
}

// ---------------- launcher --------------------------------------------------
extern "C" void kernel_launch(void* const* d_in, const int* in_sizes, int n_in,
                              void* d_out, int out_size) {
    const int*   inp     = (const int*)  d_in[0];
    const int*   lengths = (const int*)  d_in[1];
    const float* h0      = (const float*)d_in[2];
    const float* c0      = (const float*)d_in[3];
    const float* emb     = (const float*)d_in[4];
    const float* w_ih    = (const float*)d_in[5];
    const float* w_hh    = (const float*)d_in[6];
    const float* b_ih    = (const float*)d_in[7];
    const float* b_hh    = (const float*)d_in[8];
    const float* dec_w   = (const float*)d_in[9];
    float* out = (float*)d_out;
    int wstate = (out_size >= ODIM * BATCH + 2 * BATCH * HDIM) ? 1 : 0;

    cudaFuncSetAttribute(lstm_kernel, cudaFuncAttributeMaxDynamicSharedMemorySize, DSMEM);

    prep_proj_kernel<<<500 * 16, 256>>>(emb, w_ih, b_ih, b_hh);
    lstm_kernel<<<NCTA, 256, DSMEM>>>(inp, lengths, h0, c0, w_hh, out, wstate);
    decode_kernel<<<64, 256>>>(dec_w, out);
}